// round 15
// baseline (speedup 1.0000x reference)
#include <cuda_runtime.h>
#include <cuda_fp16.h>
#include <cstdint>

#define B_   8
#define K_   8
#define T_   2048
#define CS_  512
#define CH_  128
#define DIM_ 1024

// ---------------- device scratch ----------------
__device__ int g_counts[K_ * CS_];
// W fragments: [k][mt(32)][kq(8)][lane(32)] uint4  (fp16 pairs)
__device__ uint4 g_w0f[K_ * 32 * 8 * 32];
__device__ uint4 g_w1f[K_ * 32 * 8 * 32];

// ---------------- helpers ----------------
// 2-term UNSCALED fp16 split of a pair: x = x0 + x1 exactly reconstructible
__device__ __forceinline__ void split2(float x0, float x1, uint32_t& p0, uint32_t& p1) {
    __half a0 = __float2half_rn(x0), b0 = __float2half_rn(x1);
    float r = x0 - __half2float(a0), s = x1 - __half2float(b0);
    __half a1 = __float2half_rn(r), b1 = __float2half_rn(s);
    p0 = ((uint32_t)(*(uint16_t*)&b0) << 16) | *(uint16_t*)&a0;
    p1 = ((uint32_t)(*(uint16_t*)&b1) << 16) | *(uint16_t*)&a1;
}

// division-free accurate log (Cephes-style): rel err ~3e-7, exact-relative near 1.
__device__ __forceinline__ float flog(float x) {
    int ix = __float_as_int(x);
    int e = (ix - 0x3f3504f3) >> 23;            // m in [sqrt(0.5), sqrt(2))
    float z = __int_as_float(ix - (e << 23)) - 1.0f;
    float y = z * z;
    float p = 7.0376836292e-2f;
    p = fmaf(p, z, -1.1514610310e-1f);
    p = fmaf(p, z,  1.1676998740e-1f);
    p = fmaf(p, z, -1.2420140846e-1f);
    p = fmaf(p, z,  1.4249322787e-1f);
    p = fmaf(p, z, -1.6668057665e-1f);
    p = fmaf(p, z,  2.0000714765e-1f);
    p = fmaf(p, z, -2.4999993993e-1f);
    p = fmaf(p, z,  3.3333331174e-1f);
    p = p * z * y;                               // z^3 * Q(z)
    p = fmaf(-0.5f, y, p);
    float r = z + p;
    float fe = (float)e;
    r = fmaf(fe, -2.12194440e-4f, r);
    return fmaf(fe, 0.693359375f, r);
}
// hybrid gumbel: accurate inner log, MUFU.LG2 outer log (abs err ~1.7e-7)
__device__ __forceinline__ float gum(float u) {
    float l1 = flog(u + 1e-10f);
    float w = 1e-10f - l1;                       // > 0 always (u < 1)
    float lg;
    asm("lg2.approx.f32 %0, %1;" : "=f"(lg) : "f"(w));
    return lg * -0.693147181f;                   // -log(w)
}

__device__ __forceinline__ void mma16816(float* c, const uint4& A, const uint2& Bf) {
    asm volatile(
        "mma.sync.aligned.m16n8k16.row.col.f32.f16.f16.f32 "
        "{%0,%1,%2,%3},{%4,%5,%6,%7},{%8,%9},{%0,%1,%2,%3};"
        : "+f"(c[0]), "+f"(c[1]), "+f"(c[2]), "+f"(c[3])
        : "r"(A.x), "r"(A.y), "r"(A.z), "r"(A.w), "r"(Bf.x), "r"(Bf.y));
}

__device__ __forceinline__ uint32_t smem_u32(const void* p) {
    uint32_t a;
    asm("{ .reg .u64 t; cvta.to.shared.u64 t, %1; cvt.u32.u64 %0, t; }" : "=r"(a) : "l"(p));
    return a;
}
#define CP_ASYNC16(sa, gp) asm volatile("cp.async.ca.shared.global [%0], [%1], 16;" :: "r"(sa), "l"(gp))
#define CP_COMMIT()        asm volatile("cp.async.commit_group;" ::: "memory")
#define CP_WAIT0()         asm volatile("cp.async.wait_group 0;" ::: "memory")

// ---------------- kernel: W -> fragment splits (+ zero counts) ----------------
__global__ void __launch_bounds__(256) wsplit_kernel(const float* __restrict__ pw) {
    const int mt = blockIdx.x, k = blockIdx.y;
    if (blockIdx.x == 0 && blockIdx.y == 0) {
        for (int i = threadIdx.x; i < K_ * CS_; i += 256) g_counts[i] = 0;
    }
    const int tid = threadIdx.x, kq = tid >> 5, lane = tid & 31;
    const int g = lane >> 2, tg = lane & 3;
    const float* base = pw + ((size_t)(k * CS_ + mt * 16)) * CH_;
    const int ch0 = kq * 16 + 2 * tg;

    float v[4][2];
    v[0][0] = base[g * CH_ + ch0];           v[0][1] = base[g * CH_ + ch0 + 1];
    v[1][0] = base[(g + 8) * CH_ + ch0];     v[1][1] = base[(g + 8) * CH_ + ch0 + 1];
    v[2][0] = base[g * CH_ + ch0 + 8];       v[2][1] = base[g * CH_ + ch0 + 9];
    v[3][0] = base[(g + 8) * CH_ + ch0 + 8]; v[3][1] = base[(g + 8) * CH_ + ch0 + 9];

    uint32_t q[4][2];
#pragma unroll
    for (int i = 0; i < 4; ++i) split2(v[i][0], v[i][1], q[i][0], q[i][1]);

    const size_t o = ((size_t)(k * 32 + mt) * 8 + kq) * 32 + lane;
    g_w0f[o] = make_uint4(q[0][0], q[1][0], q[2][0], q[3][0]);
    g_w1f[o] = make_uint4(q[0][1], q[1][1], q[2][1], q[3][1]);
}

// ---------------- main kernel ----------------
// smem: [0,65536) X frags; pb; noise stage [64][132]; redv; redi; sidx
// sx region (65536) also reused as gather transpose (66048 <= 65536+512 pb... uses first 66048 bytes incl pb slot - safe: pb dead by then)
#define SM_PB   65536
#define SM_SN   67584
#define SM_RV   101376
#define SM_RI   103424
#define SM_SIDX 105472
#define SM_TOT  105984

__global__ void __launch_bounds__(256, 2)
main_kernel(const float* __restrict__ x, const float* __restrict__ pb,
            const float* __restrict__ noise,
            const float* __restrict__ cb, float* __restrict__ out) {
    extern __shared__ char smc[];
    uint2* sx = (uint2*)smc;
    float* s_pb = (float*)(smc + SM_PB);
    float* sn   = (float*)(smc + SM_SN);      // [64 cs][132]
    float* redv = (float*)(smc + SM_RV);
    int*   redi = (int*)(smc + SM_RI);
    int*   sidx = (int*)(smc + SM_SIDX);

    const int tid = threadIdx.x, wid = tid >> 5, lane = tid & 31;
    const int g = lane >> 2, tg = lane & 3;
    const int wm = wid & 3, wn = wid >> 2;
    const int tt = blockIdx.x, k = blockIdx.y, b = blockIdx.z;
    const int bk = b * K_ + k;
    const uint32_t sn_u32 = smem_u32(sn);

    // ---- fused X split: build fp16 fragment images in smem directly from x ----
    {
        const float* xb = x + ((size_t)(b * DIM_ + k * CH_)) * T_ + tt * 128;
        const int kq = wid;                       // 8 warps == 8 kq slices
        const int r0 = kq * 16 + 2 * tg;
        uint2* sx0 = sx + kq * 512;
        uint2* sx1 = sx0 + 4096;
        const float* row0 = xb + (size_t)r0 * T_;
#pragma unroll
        for (int nt = 0; nt < 16; ++nt) {
            const int t = nt * 8 + g;
            float v0 = row0[t];
            float v1 = row0[T_ + t];
            float v8 = row0[(size_t)8 * T_ + t];
            float v9 = row0[(size_t)9 * T_ + t];
            uint32_t p0a, p0b, p1a, p1b;
            split2(v0, v1, p0a, p0b);
            split2(v8, v9, p1a, p1b);
            sx0[nt * 32 + lane] = make_uint2(p0a, p1a);
            sx1[nt * 32 + lane] = make_uint2(p0b, p1b);
        }
    }
    for (int i = tid; i < 512; i += 256) {
        s_pb[i] = pb[k * CS_ + i];
        redv[i] = -3.4e38f;
        redi[i] = 0;
    }

    const float* ngbase = noise + (size_t)bk * CS_ * T_ + tt * 128;

    // prefetch noise tile for m=0
    {
        const float* ng = ngbase;
        for (int idx = tid; idx < 2048; idx += 256) {
            const int row = idx >> 5, col = idx & 31;
            CP_ASYNC16(sn_u32 + (uint32_t)(row * 132 + col * 4) * 4,
                       ng + (size_t)row * T_ + col * 4);
        }
        CP_COMMIT();
    }
    __syncthreads();

    // 8 chunks of 64 cs; each warp owns one 16-cs m-tile (wm) and 64-t half (wn)
    for (int m = 0; m < 8; ++m) {
        float acc[32];
#pragma unroll
        for (int i = 0; i < 32; ++i) acc[i] = 0.0f;

        const int mt = m * 4 + wm;
        const int wo = (k * 32 + mt) * 256 + lane;
        const uint2* bp0 = sx + wn * 256 + lane;

        // ---- fused pass: w0x0 + w1x0 + w0x1 (w1x1 ~2^-22, dropped) ----
#pragma unroll
        for (int kq = 0; kq < 8; ++kq) {
            const int ai = wo + kq * 32;
            uint4 a0 = g_w0f[ai];
            uint4 a1 = g_w1f[ai];
            const uint2* bq = bp0 + kq * 512;
#pragma unroll
            for (int j = 0; j < 8; ++j) {
                uint2 b0 = bq[j * 32];
                uint2 b1 = bq[4096 + j * 32];
                float* c0 = &acc[j * 4];
                mma16816(c0, a0, b0);
                mma16816(c0, a1, b0);
                mma16816(c0, a0, b1);
            }
        }

        // noise tile for this m is in flight; wait + make visible
        CP_WAIT0();
        __syncthreads();

        // ---- epilogue: bias + gumbel (smem noise) + warp argmax ----
        const int cs0 = m * 64 + wm * 16 + g;
        const float bb0 = s_pb[cs0], bb1 = s_pb[cs0 + 8];
        const float* snr = sn + (wm * 16 + g) * 132 + wn * 64 + 2 * tg;
#pragma unroll
        for (int j = 0; j < 8; ++j) {
            float2 n0 = *(const float2*)(snr + j * 8);
            float2 n1 = *(const float2*)(snr + 8 * 132 + j * 8);
            float v00 = acc[j * 4 + 0] + bb0 + gum(n0.x);
            float v01 = acc[j * 4 + 1] + bb0 + gum(n0.y);
            float v10 = acc[j * 4 + 2] + bb1 + gum(n1.x);
            float v11 = acc[j * 4 + 3] + bb1 + gum(n1.y);
#pragma unroll
            for (int c = 0; c < 2; ++c) {
                float bv = c ? v01 : v00; int bi = cs0;
                float v1c = c ? v11 : v10;
                if (v1c > bv) { bv = v1c; bi = cs0 + 8; }
#pragma unroll
                for (int msk = 4; msk <= 16; msk <<= 1) {
                    float ov = __shfl_xor_sync(0xffffffffu, bv, msk);
                    int   oi = __shfl_xor_sync(0xffffffffu, bi, msk);
                    if (ov > bv || (ov == bv && oi < bi)) { bv = ov; bi = oi; }
                }
                if (lane < 4) {
                    const int tl = wn * 64 + j * 8 + 2 * tg + c;
                    const int slot = tl * 4 + wm;
                    float cv = redv[slot];
                    int   ci = redi[slot];
                    if (bv > cv || (bv == cv && bi < ci)) { redv[slot] = bv; redi[slot] = bi; }
                }
            }
        }

        // all reads of sn done -> start next tile's prefetch
        __syncthreads();
        if (m < 7) {
            const float* ng = ngbase + (size_t)((m + 1) * 64) * T_;
            for (int idx = tid; idx < 2048; idx += 256) {
                const int row = idx >> 5, col = idx & 31;
                CP_ASYNC16(sn_u32 + (uint32_t)(row * 132 + col * 4) * 4,
                           ng + (size_t)row * T_ + col * 4);
            }
            CP_COMMIT();
        }
    }

    __syncthreads();
    if (tid < 128) {
        float fv = -3.4e38f; int fi = 0;
#pragma unroll
        for (int s2 = 0; s2 < 4; ++s2) {
            float v = redv[tid * 4 + s2];
            int id = redi[tid * 4 + s2];
            if (v > fv || (v == fv && id < fi)) { fv = v; fi = id; }
        }
        sidx[tid] = fi;
        atomicAdd(&g_counts[k * CS_ + fi], 1);
    }
    __syncthreads();

    // ---- fused gather: codebook rows -> transpose -> coalesced out ----
    {
        float* smT = (float*)smc;                       // [128 c][129]
        const int c = tid & 127, rh = tid >> 7;
        const float* cbk_ = cb + (size_t)k * CS_ * CH_;
#pragma unroll 4
        for (int it = 0; it < 64; ++it) {
            const int r = it * 2 + rh;                  // t within tile
            smT[c * 129 + r] = cbk_[(size_t)sidx[r] * CH_ + c];
        }
        __syncthreads();
        const int t2 = (tid & 63) * 2, c0 = tid >> 6;
        float* og = out + ((size_t)b * DIM_ + (size_t)k * CH_) * T_ + tt * 128;
#pragma unroll 8
        for (int i = 0; i < 32; ++i) {
            const int cc = c0 * 32 + i;
            float2 v = make_float2(smT[cc * 129 + t2], smT[cc * 129 + t2 + 1]);
            *(float2*)(og + (size_t)cc * T_ + t2) = v;
        }
    }
}

// ---------------- perplexity: block per k ----------------
__global__ void __launch_bounds__(512) perplexity_kernel(float* __restrict__ out) {
    __shared__ float red[16];
    const int k = blockIdx.x, tid = threadIdx.x;
    float p = (float)g_counts[k * CS_ + tid] * (1.0f / (B_ * T_));
    float s = -p * logf(p + 1e-8f);
#pragma unroll
    for (int o = 16; o; o >>= 1) s += __shfl_down_sync(0xffffffffu, s, o);
    if ((tid & 31) == 0) red[tid >> 5] = s;
    __syncthreads();
    if (tid < 16) {
        s = red[tid];
#pragma unroll
        for (int o = 8; o; o >>= 1) s += __shfl_down_sync(0xffffu, s, o);
        if (tid == 0) out[(size_t)B_ * DIM_ * T_ + k] = expf(s);
    }
}

extern "C" void kernel_launch(void* const* d_in, const int* in_sizes, int n_in,
                              void* d_out, int out_size) {
    const float* x     = (const float*)d_in[0];
    const float* pw    = (const float*)d_in[1];
    const float* pb    = (const float*)d_in[2];
    const float* cbk   = (const float*)d_in[3];
    const float* noise = (const float*)d_in[4];
    float* out = (float*)d_out;

    cudaFuncSetAttribute(main_kernel, cudaFuncAttributeMaxDynamicSharedMemorySize, SM_TOT);

    wsplit_kernel<<<dim3(32, K_), 256>>>(pw);
    main_kernel<<<dim3(16, K_, B_), 256, SM_TOT>>>(x, pb, noise, cbk, out);
    perplexity_kernel<<<K_, 512>>>(out);
}

// round 16
// speedup vs baseline: 1.2243x; 1.2243x over previous
#include <cuda_runtime.h>
#include <cuda_fp16.h>
#include <cstdint>

#define B_   8
#define K_   8
#define T_   2048
#define CS_  512
#define CH_  128
#define DIM_ 1024

// ---------------- device scratch ----------------
__device__ int g_counts[K_ * CS_];
// W fragments: [k][mt(32)][kq(8)][lane(32)] uint4  (fp16 pairs)
__device__ uint4 g_w0f[K_ * 32 * 8 * 32];
__device__ uint4 g_w1f[K_ * 32 * 8 * 32];

// ---------------- helpers ----------------
// 2-term UNSCALED fp16 split of a pair: x = x0 + x1 exactly reconstructible
__device__ __forceinline__ void split2(float x0, float x1, uint32_t& p0, uint32_t& p1) {
    __half a0 = __float2half_rn(x0), b0 = __float2half_rn(x1);
    float r = x0 - __half2float(a0), s = x1 - __half2float(b0);
    __half a1 = __float2half_rn(r), b1 = __float2half_rn(s);
    p0 = ((uint32_t)(*(uint16_t*)&b0) << 16) | *(uint16_t*)&a0;
    p1 = ((uint32_t)(*(uint16_t*)&b1) << 16) | *(uint16_t*)&a1;
}

// division-free accurate log (Cephes-style): rel err ~3e-7, exact-relative near 1.
__device__ __forceinline__ float flog(float x) {
    int ix = __float_as_int(x);
    int e = (ix - 0x3f3504f3) >> 23;            // m in [sqrt(0.5), sqrt(2))
    float z = __int_as_float(ix - (e << 23)) - 1.0f;
    float y = z * z;
    float p = 7.0376836292e-2f;
    p = fmaf(p, z, -1.1514610310e-1f);
    p = fmaf(p, z,  1.1676998740e-1f);
    p = fmaf(p, z, -1.2420140846e-1f);
    p = fmaf(p, z,  1.4249322787e-1f);
    p = fmaf(p, z, -1.6668057665e-1f);
    p = fmaf(p, z,  2.0000714765e-1f);
    p = fmaf(p, z, -2.4999993993e-1f);
    p = fmaf(p, z,  3.3333331174e-1f);
    p = p * z * y;                               // z^3 * Q(z)
    p = fmaf(-0.5f, y, p);
    float r = z + p;
    float fe = (float)e;
    r = fmaf(fe, -2.12194440e-4f, r);
    return fmaf(fe, 0.693359375f, r);
}
// hybrid gumbel: accurate inner log, MUFU.LG2 outer log (abs err ~1.7e-7)
__device__ __forceinline__ float gum(float u) {
    float l1 = flog(u + 1e-10f);
    float w = 1e-10f - l1;                       // > 0 always (u < 1)
    float lg;
    asm("lg2.approx.f32 %0, %1;" : "=f"(lg) : "f"(w));
    return lg * -0.693147181f;                   // -log(w)
}

__device__ __forceinline__ void mma16816(float* c, const uint4& A, const uint2& Bf) {
    asm volatile(
        "mma.sync.aligned.m16n8k16.row.col.f32.f16.f16.f32 "
        "{%0,%1,%2,%3},{%4,%5,%6,%7},{%8,%9},{%0,%1,%2,%3};"
        : "+f"(c[0]), "+f"(c[1]), "+f"(c[2]), "+f"(c[3])
        : "r"(A.x), "r"(A.y), "r"(A.z), "r"(A.w), "r"(Bf.x), "r"(Bf.y));
}

// ---------------- kernel: W -> fragment splits (+ zero counts) ----------------
__global__ void __launch_bounds__(256) wsplit_kernel(const float* __restrict__ pw) {
    const int mt = blockIdx.x, k = blockIdx.y;
    if (blockIdx.x == 0 && blockIdx.y == 0) {
        for (int i = threadIdx.x; i < K_ * CS_; i += 256) g_counts[i] = 0;
    }
    const int tid = threadIdx.x, kq = tid >> 5, lane = tid & 31;
    const int g = lane >> 2, tg = lane & 3;
    const float* base = pw + ((size_t)(k * CS_ + mt * 16)) * CH_;
    const int ch0 = kq * 16 + 2 * tg;

    float v[4][2];
    v[0][0] = base[g * CH_ + ch0];           v[0][1] = base[g * CH_ + ch0 + 1];
    v[1][0] = base[(g + 8) * CH_ + ch0];     v[1][1] = base[(g + 8) * CH_ + ch0 + 1];
    v[2][0] = base[g * CH_ + ch0 + 8];       v[2][1] = base[g * CH_ + ch0 + 9];
    v[3][0] = base[(g + 8) * CH_ + ch0 + 8]; v[3][1] = base[(g + 8) * CH_ + ch0 + 9];

    uint32_t q[4][2];
#pragma unroll
    for (int i = 0; i < 4; ++i) split2(v[i][0], v[i][1], q[i][0], q[i][1]);

    const size_t o = ((size_t)(k * 32 + mt) * 8 + kq) * 32 + lane;
    g_w0f[o] = make_uint4(q[0][0], q[1][0], q[2][0], q[3][0]);
    g_w1f[o] = make_uint4(q[0][1], q[1][1], q[2][1], q[3][1]);
}

// ---------------- main kernel ----------------
// 128 threads (4 warps), 64-t tile. smem layout (bytes):
//   sx   [0, 32768): X frag images (x0: 2048 uint2, x1: 2048 uint2)
//   pb   [32768, 34816)
//   redv [34816, 35840)   [64 t][4 wm]
//   redi [35840, 36864)
//   sidx [36864, 37120)
// gather reuses [0, 33280) as [128 c][65] floats (sx+pb dead by then)
#define SM_PB   32768
#define SM_RV   34816
#define SM_RI   35840
#define SM_SIDX 36864
#define SM_TOT  37120

__global__ void __launch_bounds__(128, 6)
main_kernel(const float* __restrict__ x, const float* __restrict__ pb,
            const float* __restrict__ noise,
            const float* __restrict__ cb, float* __restrict__ out) {
    extern __shared__ char smc[];
    uint2* sx = (uint2*)smc;
    float* s_pb = (float*)(smc + SM_PB);
    float* redv = (float*)(smc + SM_RV);
    int*   redi = (int*)(smc + SM_RI);
    int*   sidx = (int*)(smc + SM_SIDX);

    const int tid = threadIdx.x, wid = tid >> 5, lane = tid & 31;
    const int g = lane >> 2, tg = lane & 3;
    const int tt = blockIdx.x, k = blockIdx.y, b = blockIdx.z;
    const int bk = b * K_ + k;

    // ---- fused X split: build fp16 fragment images in smem directly from x ----
    // sx0 layout: [kq(8)][nt(8)][lane(32)] uint2 ; sx1 at +2048 uint2
    {
        const float* xb = x + ((size_t)(b * DIM_ + k * CH_)) * T_ + tt * 64;
#pragma unroll
        for (int kq2 = 0; kq2 < 2; ++kq2) {
            const int kq = wid * 2 + kq2;
            const int r0 = kq * 16 + 2 * tg;
            uint2* sx0 = sx + kq * 256;
            uint2* sx1 = sx0 + 2048;
            const float* row0 = xb + (size_t)r0 * T_;
#pragma unroll
            for (int nt = 0; nt < 8; ++nt) {
                const int t = nt * 8 + g;
                float v0 = row0[t];
                float v1 = row0[T_ + t];
                float v8 = row0[(size_t)8 * T_ + t];
                float v9 = row0[(size_t)9 * T_ + t];
                uint32_t p0a, p0b, p1a, p1b;
                split2(v0, v1, p0a, p0b);
                split2(v8, v9, p1a, p1b);
                sx0[nt * 32 + lane] = make_uint2(p0a, p1a);
                sx1[nt * 32 + lane] = make_uint2(p0b, p1b);
            }
        }
    }
    for (int i = tid; i < 512; i += 128) s_pb[i] = pb[k * CS_ + i];
    for (int i = tid; i < 256; i += 128) { redv[i] = -3.4e38f; redi[i] = 0; }
    __syncthreads();

    const float* nbase = noise + (size_t)bk * CS_ * T_ + tt * 64 + 2 * tg;

    // 8 chunks of 64 cs; each warp owns one 16-cs m-tile (wid), full 64-t width
    for (int m = 0; m < 8; ++m) {
        float acc[32];
#pragma unroll
        for (int i = 0; i < 32; ++i) acc[i] = 0.0f;

        const int mt = m * 4 + wid;
        const int wo = (k * 32 + mt) * 256 + lane;
        const uint2* bp0 = sx + lane;

        // ---- fused pass: w0x0 + w1x0 + w0x1 (w1x1 ~2^-22, dropped) ----
#pragma unroll
        for (int kq = 0; kq < 8; ++kq) {
            const int ai = wo + kq * 32;
            uint4 a0 = g_w0f[ai];
            uint4 a1 = g_w1f[ai];
            const uint2* bq = bp0 + kq * 256;
#pragma unroll
            for (int j = 0; j < 8; ++j) {
                uint2 b0 = bq[j * 32];
                uint2 b1 = bq[2048 + j * 32];
                float* c0 = &acc[j * 4];
                mma16816(c0, a0, b0);
                mma16816(c0, a1, b0);
                mma16816(c0, a0, b1);
            }
        }

        // ---- epilogue: bias + gumbel + warp argmax ----
        const int cs0 = m * 64 + wid * 16 + g;
        const float bb0 = s_pb[cs0], bb1 = s_pb[cs0 + 8];
        const float* nrow = nbase + (size_t)cs0 * T_;
#pragma unroll
        for (int j = 0; j < 8; ++j) {
            float2 n0 = *(const float2*)(nrow + j * 8);
            float2 n1 = *(const float2*)(nrow + (size_t)8 * T_ + j * 8);
            float v00 = acc[j * 4 + 0] + bb0 + gum(n0.x);
            float v01 = acc[j * 4 + 1] + bb0 + gum(n0.y);
            float v10 = acc[j * 4 + 2] + bb1 + gum(n1.x);
            float v11 = acc[j * 4 + 3] + bb1 + gum(n1.y);
#pragma unroll
            for (int c = 0; c < 2; ++c) {
                float bv = c ? v01 : v00; int bi = cs0;
                float v1c = c ? v11 : v10;
                if (v1c > bv) { bv = v1c; bi = cs0 + 8; }
#pragma unroll
                for (int msk = 4; msk <= 16; msk <<= 1) {
                    float ov = __shfl_xor_sync(0xffffffffu, bv, msk);
                    int   oi = __shfl_xor_sync(0xffffffffu, bi, msk);
                    if (ov > bv || (ov == bv && oi < bi)) { bv = ov; bi = oi; }
                }
                if (lane < 4) {
                    const int tl = j * 8 + 2 * tg + c;
                    const int slot = tl * 4 + wid;
                    float cv = redv[slot];
                    int   ci = redi[slot];
                    if (bv > cv || (bv == cv && bi < ci)) { redv[slot] = bv; redi[slot] = bi; }
                }
            }
        }
    }

    __syncthreads();
    if (tid < 64) {
        float fv = -3.4e38f; int fi = 0;
#pragma unroll
        for (int s2 = 0; s2 < 4; ++s2) {
            float v = redv[tid * 4 + s2];
            int id = redi[tid * 4 + s2];
            if (v > fv || (v == fv && id < fi)) { fv = v; fi = id; }
        }
        sidx[tid] = fi;
        atomicAdd(&g_counts[k * CS_ + fi], 1);
    }
    __syncthreads();

    // ---- fused gather: codebook rows -> transpose -> coalesced out ----
    {
        float* smT = (float*)smc;                       // [128 c][65]
        const int c = tid;                              // 0..127
        const float* cbk_ = cb + (size_t)k * CS_ * CH_;
#pragma unroll 4
        for (int r = 0; r < 64; ++r) {
            smT[c * 65 + r] = cbk_[(size_t)sidx[r] * CH_ + c];
        }
        __syncthreads();
        const int t2 = (tid & 31) * 2, c0 = tid >> 5;   // c0 0..3
        float* og = out + ((size_t)b * DIM_ + (size_t)k * CH_) * T_ + tt * 64;
#pragma unroll 8
        for (int i = 0; i < 32; ++i) {
            const int cc = c0 * 32 + i;
            float2 v = make_float2(smT[cc * 65 + t2], smT[cc * 65 + t2 + 1]);
            *(float2*)(og + (size_t)cc * T_ + t2) = v;
        }
    }
}

// ---------------- perplexity: block per k ----------------
__global__ void __launch_bounds__(512) perplexity_kernel(float* __restrict__ out) {
    __shared__ float red[16];
    const int k = blockIdx.x, tid = threadIdx.x;
    float p = (float)g_counts[k * CS_ + tid] * (1.0f / (B_ * T_));
    float s = -p * logf(p + 1e-8f);
#pragma unroll
    for (int o = 16; o; o >>= 1) s += __shfl_down_sync(0xffffffffu, s, o);
    if ((tid & 31) == 0) red[tid >> 5] = s;
    __syncthreads();
    if (tid < 16) {
        s = red[tid];
#pragma unroll
        for (int o = 8; o; o >>= 1) s += __shfl_down_sync(0xffffu, s, o);
        if (tid == 0) out[(size_t)B_ * DIM_ * T_ + k] = expf(s);
    }
}

extern "C" void kernel_launch(void* const* d_in, const int* in_sizes, int n_in,
                              void* d_out, int out_size) {
    const float* x     = (const float*)d_in[0];
    const float* pw    = (const float*)d_in[1];
    const float* pb    = (const float*)d_in[2];
    const float* cbk   = (const float*)d_in[3];
    const float* noise = (const float*)d_in[4];
    float* out = (float*)d_out;

    cudaFuncSetAttribute(main_kernel, cudaFuncAttributeMaxDynamicSharedMemorySize, SM_TOT);

    wsplit_kernel<<<dim3(32, K_), 256>>>(pw);
    main_kernel<<<dim3(32, K_, B_), 128, SM_TOT>>>(x, pb, noise, cbk, out);
    perplexity_kernel<<<K_, 512>>>(out);
}

// round 17
// speedup vs baseline: 1.6817x; 1.3735x over previous
#include <cuda_runtime.h>
#include <cuda_fp16.h>
#include <cstdint>

#define B_   8
#define K_   8
#define T_   2048
#define CS_  512
#define CH_  128
#define DIM_ 1024

// ---------------- device scratch ----------------
__device__ int g_counts[K_ * CS_];
// W fragments: [k][mt(32)][kq(8)][lane(32)] uint4  (fp16 pairs)
__device__ uint4 g_w0f[K_ * 32 * 8 * 32];
__device__ uint4 g_w1f[K_ * 32 * 8 * 32];

// ---------------- helpers ----------------
// 2-term UNSCALED fp16 split of a pair: x = x0 + x1 exactly reconstructible
__device__ __forceinline__ void split2(float x0, float x1, uint32_t& p0, uint32_t& p1) {
    __half a0 = __float2half_rn(x0), b0 = __float2half_rn(x1);
    float r = x0 - __half2float(a0), s = x1 - __half2float(b0);
    __half a1 = __float2half_rn(r), b1 = __float2half_rn(s);
    p0 = ((uint32_t)(*(uint16_t*)&b0) << 16) | *(uint16_t*)&a0;
    p1 = ((uint32_t)(*(uint16_t*)&b1) << 16) | *(uint16_t*)&a1;
}

// division-free accurate log (Cephes-style): rel err ~3e-7, exact-relative near 1.
__device__ __forceinline__ float flog(float x) {
    int ix = __float_as_int(x);
    int e = (ix - 0x3f3504f3) >> 23;            // m in [sqrt(0.5), sqrt(2))
    float z = __int_as_float(ix - (e << 23)) - 1.0f;
    float y = z * z;
    float p = 7.0376836292e-2f;
    p = fmaf(p, z, -1.1514610310e-1f);
    p = fmaf(p, z,  1.1676998740e-1f);
    p = fmaf(p, z, -1.2420140846e-1f);
    p = fmaf(p, z,  1.4249322787e-1f);
    p = fmaf(p, z, -1.6668057665e-1f);
    p = fmaf(p, z,  2.0000714765e-1f);
    p = fmaf(p, z, -2.4999993993e-1f);
    p = fmaf(p, z,  3.3333331174e-1f);
    p = p * z * y;                               // z^3 * Q(z)
    p = fmaf(-0.5f, y, p);
    float r = z + p;
    float fe = (float)e;
    r = fmaf(fe, -2.12194440e-4f, r);
    return fmaf(fe, 0.693359375f, r);
}
// hybrid gumbel: accurate inner log, MUFU.LG2 outer log (abs err ~1.7e-7)
__device__ __forceinline__ float gum(float u) {
    float l1 = flog(u + 1e-10f);
    float w = 1e-10f - l1;                       // > 0 always (u < 1)
    float lg;
    asm("lg2.approx.f32 %0, %1;" : "=f"(lg) : "f"(w));
    return lg * -0.693147181f;                   // -log(w)
}

__device__ __forceinline__ void mma16816(float* c, const uint4& A, const uint2& Bf) {
    asm volatile(
        "mma.sync.aligned.m16n8k16.row.col.f32.f16.f16.f32 "
        "{%0,%1,%2,%3},{%4,%5,%6,%7},{%8,%9},{%0,%1,%2,%3};"
        : "+f"(c[0]), "+f"(c[1]), "+f"(c[2]), "+f"(c[3])
        : "r"(A.x), "r"(A.y), "r"(A.z), "r"(A.w), "r"(Bf.x), "r"(Bf.y));
}

// ---------------- kernel: W -> fragment splits (+ zero counts) ----------------
__global__ void __launch_bounds__(256) wsplit_kernel(const float* __restrict__ pw) {
    const int mt = blockIdx.x, k = blockIdx.y;
    if (blockIdx.x == 0 && blockIdx.y == 0) {
        for (int i = threadIdx.x; i < K_ * CS_; i += 256) g_counts[i] = 0;
    }
    const int tid = threadIdx.x, kq = tid >> 5, lane = tid & 31;
    const int g = lane >> 2, tg = lane & 3;
    const float* base = pw + ((size_t)(k * CS_ + mt * 16)) * CH_;
    const int ch0 = kq * 16 + 2 * tg;

    float v[4][2];
    v[0][0] = base[g * CH_ + ch0];           v[0][1] = base[g * CH_ + ch0 + 1];
    v[1][0] = base[(g + 8) * CH_ + ch0];     v[1][1] = base[(g + 8) * CH_ + ch0 + 1];
    v[2][0] = base[g * CH_ + ch0 + 8];       v[2][1] = base[g * CH_ + ch0 + 9];
    v[3][0] = base[(g + 8) * CH_ + ch0 + 8]; v[3][1] = base[(g + 8) * CH_ + ch0 + 9];

    uint32_t q[4][2];
#pragma unroll
    for (int i = 0; i < 4; ++i) split2(v[i][0], v[i][1], q[i][0], q[i][1]);

    const size_t o = ((size_t)(k * 32 + mt) * 8 + kq) * 32 + lane;
    g_w0f[o] = make_uint4(q[0][0], q[1][0], q[2][0], q[3][0]);
    g_w1f[o] = make_uint4(q[0][1], q[1][1], q[2][1], q[3][1]);
}

// ---------------- main kernel ----------------
// 128 threads (4 warps), 64-t tile. smem layout (bytes):
//   sx   [0, 32768): X frag images (x0: 2048 uint2, x1: 2048 uint2)
//   pb   [32768, 34816)
//   redv [34816, 35840)   [64 t][4 wm]
//   redi [35840, 36864)
//   sidx [36864, 37120)
// gather reuses [0, 33280) as [128 c][65] floats (sx+pb dead by then)
#define SM_PB   32768
#define SM_RV   34816
#define SM_RI   35840
#define SM_SIDX 36864
#define SM_TOT  37120

__global__ void __launch_bounds__(128, 5)
main_kernel(const float* __restrict__ x, const float* __restrict__ pb,
            const float* __restrict__ noise,
            const float* __restrict__ cb, float* __restrict__ out) {
    extern __shared__ char smc[];
    uint2* sx = (uint2*)smc;
    float* s_pb = (float*)(smc + SM_PB);
    float* redv = (float*)(smc + SM_RV);
    int*   redi = (int*)(smc + SM_RI);
    int*   sidx = (int*)(smc + SM_SIDX);

    const int tid = threadIdx.x, wid = tid >> 5, lane = tid & 31;
    const int g = lane >> 2, tg = lane & 3;
    const int tt = blockIdx.x, k = blockIdx.y, b = blockIdx.z;
    const int bk = b * K_ + k;

    // ---- fused X split: build fp16 fragment images in smem directly from x ----
    {
        const float* xb = x + ((size_t)(b * DIM_ + k * CH_)) * T_ + tt * 64;
#pragma unroll
        for (int kq2 = 0; kq2 < 2; ++kq2) {
            const int kq = wid * 2 + kq2;
            const int r0 = kq * 16 + 2 * tg;
            uint2* sx0 = sx + kq * 256;
            uint2* sx1 = sx0 + 2048;
            const float* row0 = xb + (size_t)r0 * T_;
#pragma unroll
            for (int nt = 0; nt < 8; ++nt) {
                const int t = nt * 8 + g;
                float v0 = __ldcs(row0 + t);
                float v1 = __ldcs(row0 + T_ + t);
                float v8 = __ldcs(row0 + (size_t)8 * T_ + t);
                float v9 = __ldcs(row0 + (size_t)9 * T_ + t);
                uint32_t p0a, p0b, p1a, p1b;
                split2(v0, v1, p0a, p0b);
                split2(v8, v9, p1a, p1b);
                sx0[nt * 32 + lane] = make_uint2(p0a, p1a);
                sx1[nt * 32 + lane] = make_uint2(p0b, p1b);
            }
        }
    }
    for (int i = tid; i < 512; i += 128) s_pb[i] = pb[k * CS_ + i];
    __syncthreads();

    const float* nbase = noise + (size_t)bk * CS_ * T_ + tt * 64 + 2 * tg;

    // per-thread running argmax over all 8 m-chunks: 16 t-cols, code = m*2+row
    float bv[16];
    int   bi[16];
#pragma unroll
    for (int i = 0; i < 16; ++i) { bv[i] = -3.4e38f; bi[i] = 0; }

    // 8 chunks of 64 cs; each warp owns one 16-cs m-tile (wid), full 64-t width
    for (int m = 0; m < 8; ++m) {
        float acc[32];
#pragma unroll
        for (int i = 0; i < 32; ++i) acc[i] = 0.0f;

        const int mt = m * 4 + wid;
        const int wo = (k * 32 + mt) * 256 + lane;
        const uint2* bp0 = sx + lane;

        // ---- fused pass: w0x0 + w1x0 + w0x1 (w1x1 ~2^-22, dropped) ----
#pragma unroll
        for (int kq = 0; kq < 8; ++kq) {
            const int ai = wo + kq * 32;
            uint4 a0 = g_w0f[ai];
            uint4 a1 = g_w1f[ai];
            const uint2* bq = bp0 + kq * 256;
#pragma unroll
            for (int j = 0; j < 8; ++j) {
                uint2 b0 = bq[j * 32];
                uint2 b1 = bq[2048 + j * 32];
                float* c0 = &acc[j * 4];
                mma16816(c0, a0, b0);
                mma16816(c0, a1, b0);
                mma16816(c0, a0, b1);
            }
        }

        // ---- epilogue: bias + gumbel + per-thread argmax update (no shfl) ----
        const int cs0 = m * 64 + wid * 16 + g;
        const float bb0 = s_pb[cs0], bb1 = s_pb[cs0 + 8];
        const float* nrow = nbase + (size_t)cs0 * T_;
        const int code0 = m * 2, code1 = m * 2 + 1;
#pragma unroll
        for (int j = 0; j < 8; ++j) {
            float2 n0 = __ldcs((const float2*)(nrow + j * 8));
            float2 n1 = __ldcs((const float2*)(nrow + (size_t)8 * T_ + j * 8));
            float v00 = acc[j * 4 + 0] + bb0 + gum(n0.x);
            float v01 = acc[j * 4 + 1] + bb0 + gum(n0.y);
            float v10 = acc[j * 4 + 2] + bb1 + gum(n1.x);
            float v11 = acc[j * 4 + 3] + bb1 + gum(n1.y);
            const int t0 = j * 2, t1 = j * 2 + 1;
            if (v00 > bv[t0]) { bv[t0] = v00; bi[t0] = code0; }
            if (v10 > bv[t0]) { bv[t0] = v10; bi[t0] = code1; }
            if (v01 > bv[t1]) { bv[t1] = v01; bi[t1] = code0; }
            if (v11 > bv[t1]) { bv[t1] = v11; bi[t1] = code1; }
        }
    }

    // ---- single warp reduction per t-col (decode code -> global cs first) ----
#pragma unroll
    for (int tc = 0; tc < 16; ++tc) {
        float v = bv[tc];
        int code = bi[tc];
        int id = (code >> 1) * 64 + wid * 16 + g + (code & 1) * 8;
#pragma unroll
        for (int msk = 4; msk <= 16; msk <<= 1) {
            float ov = __shfl_xor_sync(0xffffffffu, v, msk);
            int   oi = __shfl_xor_sync(0xffffffffu, id, msk);
            if (ov > v || (ov == v && oi < id)) { v = ov; id = oi; }
        }
        if (lane < 4) {
            const int tl = (tc >> 1) * 8 + 2 * tg + (tc & 1);
            redv[tl * 4 + wid] = v;
            redi[tl * 4 + wid] = id;
        }
    }

    __syncthreads();
    if (tid < 64) {
        float fv = -3.4e38f; int fi = 0;
#pragma unroll
        for (int s2 = 0; s2 < 4; ++s2) {
            float v = redv[tid * 4 + s2];
            int id = redi[tid * 4 + s2];
            if (v > fv || (v == fv && id < fi)) { fv = v; fi = id; }
        }
        sidx[tid] = fi;
        atomicAdd(&g_counts[k * CS_ + fi], 1);
    }
    __syncthreads();

    // ---- fused gather: codebook rows -> transpose -> coalesced out ----
    {
        float* smT = (float*)smc;                       // [128 c][65]
        const int c = tid;                              // 0..127
        const float* cbk_ = cb + (size_t)k * CS_ * CH_;
#pragma unroll 4
        for (int r = 0; r < 64; ++r) {
            smT[c * 65 + r] = cbk_[(size_t)sidx[r] * CH_ + c];
        }
        __syncthreads();
        const int t2 = (tid & 31) * 2, c0 = tid >> 5;   // c0 0..3
        float* og = out + ((size_t)b * DIM_ + (size_t)k * CH_) * T_ + tt * 64;
#pragma unroll 8
        for (int i = 0; i < 32; ++i) {
            const int cc = c0 * 32 + i;
            float2 v = make_float2(smT[cc * 65 + t2], smT[cc * 65 + t2 + 1]);
            *(float2*)(og + (size_t)cc * T_ + t2) = v;
        }
    }
}

// ---------------- perplexity: block per k ----------------
__global__ void __launch_bounds__(512) perplexity_kernel(float* __restrict__ out) {
    __shared__ float red[16];
    const int k = blockIdx.x, tid = threadIdx.x;
    float p = (float)g_counts[k * CS_ + tid] * (1.0f / (B_ * T_));
    float s = -p * logf(p + 1e-8f);
#pragma unroll
    for (int o = 16; o; o >>= 1) s += __shfl_down_sync(0xffffffffu, s, o);
    if ((tid & 31) == 0) red[tid >> 5] = s;
    __syncthreads();
    if (tid < 16) {
        s = red[tid];
#pragma unroll
        for (int o = 8; o; o >>= 1) s += __shfl_down_sync(0xffffu, s, o);
        if (tid == 0) out[(size_t)B_ * DIM_ * T_ + k] = expf(s);
    }
}

extern "C" void kernel_launch(void* const* d_in, const int* in_sizes, int n_in,
                              void* d_out, int out_size) {
    const float* x     = (const float*)d_in[0];
    const float* pw    = (const float*)d_in[1];
    const float* pb    = (const float*)d_in[2];
    const float* cbk   = (const float*)d_in[3];
    const float* noise = (const float*)d_in[4];
    float* out = (float*)d_out;

    cudaFuncSetAttribute(main_kernel, cudaFuncAttributeMaxDynamicSharedMemorySize, SM_TOT);

    wsplit_kernel<<<dim3(32, K_), 256>>>(pw);
    main_kernel<<<dim3(32, K_, B_), 128, SM_TOT>>>(x, pb, noise, cbk, out);
    perplexity_kernel<<<K_, 512>>>(out);
}